// round 3
// baseline (speedup 1.0000x reference)
#include <cuda_runtime.h>
#include <cstdint>

#define Bb 16
#define Nn 16
#define Hh 512
#define Ww 512
#define HW (Hh * Ww)
#define HW4 (HW / 4)            // 65536 float4 per (b,n) slice
#define W4 (Ww / 4)             // 128 float4 per row
#define THREADS 256
#define ROWS 8                  // image rows per block
#define CHUNKS_PER_B (Hh / ROWS)        // 64
#define CHUNK_F4 (ROWS * W4)            // 1024 float4 per chunk
#define PER_THREAD (CHUNK_F4 / THREADS) // 4
#define GRID (Bb * CHUNKS_PER_B)        // 1024 blocks

// global accumulators (zero-initialized at module load; self-reset each run)
__device__ float    g_ov[Bb * Nn];
__device__ float    g_it[Bb * Nn];
__device__ float    g_ts[Bb];
__device__ unsigned g_done;

__global__ __launch_bounds__(THREADS)
void fused_kernel(const float* __restrict__ masks,
                  const float* __restrict__ target,
                  const int*   __restrict__ boxes,
                  float*       __restrict__ out)
{
    const int blk   = blockIdx.x;        // 0..1023
    const int b     = blk >> 6;          // / CHUNKS_PER_B
    const int chunk = blk & (CHUNKS_PER_B - 1);
    const int r0    = chunk * ROWS;

    const int tid = threadIdx.x;
    const int wid = tid >> 5;
    const int lid = tid & 31;
    const unsigned FULL = 0xFFFFFFFFu;

    // ---- load this thread's target elements ONCE into registers ----
    const float4* __restrict__ t =
        reinterpret_cast<const float4*>(target) + (size_t)b * HW4 + (size_t)chunk * CHUNK_F4;

    float4 tv[PER_THREAD];
    float ts = 0.f;
    #pragma unroll
    for (int k = 0; k < PER_THREAD; k++) {
        tv[k] = t[tid + k * THREADS];
        ts += (tv[k].x + tv[k].y) + (tv[k].z + tv[k].w);
    }
    // j = tid + k*256 -> column part (j & 127) is k-invariant; row advances by 2 per k
    const int w0 = (tid & (W4 - 1)) << 2;        // first column of the float4
    const int h0 = r0 + (tid >> 7);              // row for k=0 (k adds 2 rows)

    __shared__ float s_ov[Nn][THREADS / 32];
    __shared__ float s_it[Nn][THREADS / 32];
    __shared__ float s_ts[THREADS / 32];

    // warp-reduce ts now
    #pragma unroll
    for (int off = 16; off > 0; off >>= 1) ts += __shfl_xor_sync(FULL, ts, off);
    if (lid == 0) s_ts[wid] = ts;

    const float4* __restrict__ mbase =
        reinterpret_cast<const float4*>(masks) + (size_t)b * Nn * HW4 + (size_t)chunk * CHUNK_F4;

    // ---- stream all 16 masks against the register-resident target ----
    for (int n = 0; n < Nn; n++) {
        const float4* __restrict__ m = mbase + (size_t)n * HW4;
        const int4 box = __ldg(reinterpret_cast<const int4*>(boxes) + b * Nn + n);
        const int x1 = box.x, y1 = box.y, x2 = box.z, y2 = box.w;

        // column selectors (k-invariant)
        const float c0 = (w0     >= x1 && w0     < x2) ? 1.f : 0.f;
        const float c1 = (w0 + 1 >= x1 && w0 + 1 < x2) ? 1.f : 0.f;
        const float c2 = (w0 + 2 >= x1 && w0 + 2 < x2) ? 1.f : 0.f;
        const float c3 = (w0 + 3 >= x1 && w0 + 3 < x2) ? 1.f : 0.f;

        float ov = 0.f, it = 0.f;
        #pragma unroll
        for (int k = 0; k < PER_THREAD; k++) {
            const float4 mv = m[tid + k * THREADS];
            ov = fmaf(mv.x, tv[k].x, ov);
            ov = fmaf(mv.y, tv[k].y, ov);
            ov = fmaf(mv.z, tv[k].z, ov);
            ov = fmaf(mv.w, tv[k].w, ov);

            const int h = h0 + 2 * k;
            if (h >= y1 && h < y2) {
                float s;
                s = fmaf(c0, tv[k].x, 0.f);
                s = fmaf(c1, tv[k].y, s);
                s = fmaf(c2, tv[k].z, s);
                s = fmaf(c3, tv[k].w, s);
                it += s;
            }
        }

        #pragma unroll
        for (int off = 16; off > 0; off >>= 1) {
            ov += __shfl_xor_sync(FULL, ov, off);
            it += __shfl_xor_sync(FULL, it, off);
        }
        if (lid == 0) { s_ov[n][wid] = ov; s_it[n][wid] = it; }
    }
    __syncthreads();

    // ---- per-block partials -> global atomics ----
    if (tid < Nn) {
        const int n = tid;
        float ov = 0.f, it = 0.f;
        #pragma unroll
        for (int w = 0; w < THREADS / 32; w++) { ov += s_ov[n][w]; it += s_it[n][w]; }
        atomicAdd(&g_ov[b * Nn + n], ov);
        atomicAdd(&g_it[b * Nn + n], it);
    } else if (tid == Nn) {
        float tsum = 0.f;
        #pragma unroll
        for (int w = 0; w < THREADS / 32; w++) tsum += s_ts[w];
        atomicAdd(&g_ts[b], tsum);
    }
    __threadfence();
    __syncthreads();

    __shared__ unsigned s_last;
    if (tid == 0) s_last = atomicAdd(&g_done, 1u);
    __syncthreads();

    // ---- last block finalizes outputs and resets accumulators ----
    if (s_last == GRID - 1) {
        const int bn = tid;                       // 0..255
        const float ov  = *(volatile float*)&g_ov[bn];
        const float it  = *(volatile float*)&g_it[bn];
        const float tsv = *(volatile float*)&g_ts[bn >> 4];
        const int4 box = reinterpret_cast<const int4*>(boxes)[bn];
        const float area = (float)(box.z - box.x) * (float)(box.w - box.y);
        const float uni = area + tsv - it;
        out[bn * 2 + 0] = ov;
        out[bn * 2 + 1] = it / (uni + 1e-8f);
        // reset for the next graph replay
        g_ov[bn] = 0.f;
        g_it[bn] = 0.f;
        if (bn < Bb) g_ts[bn] = 0.f;
        if (bn == 0) g_done = 0u;
    }
}

extern "C" void kernel_launch(void* const* d_in, const int* in_sizes, int n_in,
                              void* d_out, int out_size)
{
    const float* masks  = (const float*)d_in[0];   // (B,N,H,W) f32
    const float* target = (const float*)d_in[1];   // (B,H,W)   f32
    const int*   boxes  = (const int*)d_in[2];     // (B,N,4)   i32
    float* out = (float*)d_out;                    // (B,N,2)   f32

    fused_kernel<<<GRID, THREADS>>>(masks, target, boxes, out);
}